// round 15
// baseline (speedup 1.0000x reference)
#include <cuda_runtime.h>
#include <cuda_bf16.h>
#include <cstdint>
#include <cstddef>

#define T_ 512
#define N_ 512
#define B_ 128
#define W1 513
#define NBLK 128
#define NTHR 512

typedef unsigned long long ull;

// shared memory layout (float offsets)
#define SM_WI   0        // [128 j4][32 i][4]     16384
#define SM_WH   16384    // [128 j4][32 i][4]     16384
#define SM_CS   32768    // [16 b][520 j]          8320
#define SM_HS   41088    // [16 b][520 j]          8320
#define SM_RED  49408    // 12 grp x 8 m x 32 ull  6144
#define SM_REDF 55552    // [16 b][2]                32
#define SM_WFS  55584    // 32
#define SM_BIAS 55616    // 32
#define SM_W0S  55648    // 32
#define SM_FLOATS 55680
#define SMEM_BYTES (SM_FLOATS * 4)   // 222,720 B

// device scratch (static arrays: allocation-free)
__device__ float g_A4[(size_t)T_ * N_ * N_];   // [t][j/4][i][j%4]
__device__ float g_Wi4[(size_t)N_ * N_];       // [j/4][i][j%4] (gate cols 1..512)
__device__ float g_Wh4[(size_t)N_ * N_];
__device__ float g_c[2][(size_t)B_ * N_];      // double-buffered c-hat, [b][j]
__device__ float g_fp[2][B_ * 16];             // f partials [parity][b][i_tile]
__device__ float g_fbase[T_ * B_];             // bf + Wf0 * x[b,t]
__device__ unsigned g_arrive;
__device__ volatile unsigned g_gen;

// ---- f32x2 helpers ----
__device__ __forceinline__ ull pack2(float a, float b) {
    ull r; asm("mov.b64 %0, {%1, %2};" : "=l"(r) : "f"(a), "f"(b)); return r;
}
__device__ __forceinline__ void unpack2(ull v, float& a, float& b) {
    asm("mov.b64 {%0, %1}, %2;" : "=f"(a), "=f"(b) : "l"(v));
}
__device__ __forceinline__ ull fma2(ull a, ull b, ull c) {
    ull d; asm("fma.rn.f32x2 %0, %1, %2, %3;" : "=l"(d) : "l"(a), "l"(b), "l"(c)); return d;
}
__device__ __forceinline__ ull add2(ull a, ull b) {
    ull d; asm("add.rn.f32x2 %0, %1, %2;" : "=l"(d) : "l"(a), "l"(b)); return d;
}

__device__ __forceinline__ void grid_barrier() {
    __syncthreads();
    if (threadIdx.x == 0) {
        unsigned old = g_gen;
        __threadfence();
        if (atomicAdd(&g_arrive, 1u) == (unsigned)(NBLK - 1)) {
            atomicExch(&g_arrive, 0u);
            __threadfence();
            g_gen = old + 1u;
        } else {
            while (g_gen == old) { }
        }
    }
    __syncthreads();
    __threadfence();
}

// ---------------------------------------------------------------------------
// Pre-pass: repack A_stack[t][i][j] -> g_A4[t][j/4][i][j%4]
// ---------------------------------------------------------------------------
__global__ void k_apack(const float* __restrict__ A) {
    __shared__ float tile[32][33];
    int t  = blockIdx.z;
    int j0 = blockIdx.x << 5, i0 = blockIdx.y << 5;
    int tx = threadIdx.x, ty = threadIdx.y;
    const float* src = A + ((size_t)t * N_ + i0) * N_ + j0;
#pragma unroll
    for (int r = 0; r < 4; ++r)
        tile[ty + r * 8][tx] = src[(size_t)(ty + r * 8) * N_ + tx];
    __syncthreads();
#pragma unroll
    for (int r = 0; r < 4; ++r) {
        int e   = (ty * 32 + tx) + (r << 8);   // 0..1023
        int j4L = e >> 7;
        int rem = e & 127;
        int iL  = rem >> 2;
        int k   = e & 3;
        g_A4[(((size_t)t * 128 + (j0 >> 2) + j4L) * 512 + i0 + iL) * 4 + k]
            = tile[iL][j4L * 4 + k];
    }
}

// ---------------------------------------------------------------------------
// Pre-pass: repack gate weights W[i][1+j] -> [j/4][i][j%4]
// ---------------------------------------------------------------------------
__global__ void k_wpack(const float* __restrict__ Wi, const float* __restrict__ Wh) {
    int idx = blockIdx.x * 256 + threadIdx.x;
    if (idx >= 2 * N_ * N_) return;
    int wsel = idx >= N_ * N_;
    int e = idx - wsel * N_ * N_;
    int j4 = e >> 11, rem = e & 2047;
    int i = rem >> 2, k = e & 3;
    const float* W = wsel ? Wh : Wi;
    float* dst = wsel ? g_Wh4 : g_Wi4;
    dst[e] = W[(size_t)i * W1 + 1 + j4 * 4 + k];
}

// ---------------------------------------------------------------------------
// Pre-pass: per-launch re-init of mutable state (graph-replay safe)
// ---------------------------------------------------------------------------
__global__ void k_init(const float* __restrict__ x, const float* __restrict__ c0,
                       const float* __restrict__ Wf, const float* __restrict__ bf) {
    int idx = blockIdx.x * blockDim.x + threadIdx.x;
    if (idx < B_ * N_) g_c[0][idx] = c0[idx];
    if (idx < T_ * B_) {
        int t = idx >> 7, b = idx & 127;
        g_fbase[idx] = __ldg(&bf[0]) + __ldg(&Wf[0]) * __ldg(&x[(size_t)b * T_ + t]);
    }
}

// ---------------------------------------------------------------------------
// Main persistent kernel: 128 blocks x 512 threads (16 warps).
// block = (it: 32 i-cols) x (bt: 16 batches)
// warp w: kq = w&7 (j in [64kq,64kq+64)), bh = w>>3 (batch half)
// lane: ig = lane&7, bg = lane>>3
// thread outputs: i = i0 + ig + 8r (r<4), b = bb0 + 8bh + bg + 4s (s<2)
// ---------------------------------------------------------------------------
__global__ void __launch_bounds__(NTHR, 1)
hippo_main(const float* __restrict__ x,  const float* __restrict__ h0,
           const float* __restrict__ Wi, const float* __restrict__ bi,
           const float* __restrict__ Wh, const float* __restrict__ bh_,
           const float* __restrict__ Wf, const float* __restrict__ B_st,
           float* __restrict__ out) {
    extern __shared__ float sm[];
    float* wf_s   = sm + SM_WFS;
    float* bias_s = sm + SM_BIAS;
    float* w0_s   = sm + SM_W0S;
    float* redf   = sm + SM_REDF;
    ull*   red    = (ull*)(sm + SM_RED);

    const int tid = threadIdx.x;
    const int it  = blockIdx.x >> 3;
    const int bt  = blockIdx.x & 7;
    const int i0  = it << 5;
    const int bb0 = bt << 4;

    // one-time weight staging (packed layout; fully coalesced both sides)
    for (int s = tid; s < 16384; s += NTHR) {
        int j4 = s >> 7, rem = s & 127;
        sm[SM_WI + s] = __ldg(&g_Wi4[(size_t)j4 * 2048 + i0 * 4 + rem]);
        sm[SM_WH + s] = __ldg(&g_Wh4[(size_t)j4 * 2048 + i0 * 4 + rem]);
    }
    if (tid < 32) {
        wf_s[tid]   = __ldg(&Wf[1 + i0 + tid]);
        bias_s[tid] = __ldg(&bi[i0 + tid]) + __ldg(&bh_[i0 + tid]);
        w0_s[tid]   = __ldg(&Wi[(size_t)(i0 + tid) * W1]) + __ldg(&Wh[(size_t)(i0 + tid) * W1]);
    }
    __syncthreads();

    const int lane = tid & 31;
    const int w    = tid >> 5;        // 0..15
    const int kq   = w & 7;
    const int bh   = w >> 3;
    const int ig   = lane & 7;
    const int bg   = lane >> 3;
    const int j4b  = kq << 4;

    const ulonglong2* wiq0 = (const ulonglong2*)(sm + SM_WI) + j4b * 32 + ig;
    const ulonglong2* whq0 = (const ulonglong2*)(sm + SM_WH) + j4b * 32 + ig;
    const ulonglong2* csq0 = (const ulonglong2*)(sm + SM_CS) + (8 * bh + bg) * 130 + j4b;
    const ulonglong2* hsq0 = (const ulonglong2*)(sm + SM_HS) + (8 * bh + bg) * 130 + j4b;

    for (int t = 0; t < T_; ++t) {
        const int rpar = t & 1, wpar = rpar ^ 1;

        // A prefetch (first j4 group) — issue before staging to bury latency
        const ulonglong2* pa = (const ulonglong2*)
            (g_A4 + ((size_t)t * 128 + j4b) * 2048) + (i0 + ig);
        ulonglong2 av[2][4];
#pragma unroll
        for (int r = 0; r < 4; ++r) av[0][r] = __ldg(pa + r * 8);

        // --- staging: warp w stages batch bL = w (f via shfl-tree) ---
        {
            int bL = w, b = bb0 + w;
            float f = 0.0f;
            if (t > 0) {
                float p = (lane < 16) ? __ldcg(&g_fp[rpar ^ 1][b * 16 + lane]) : 0.0f;
                p += __shfl_xor_sync(0xffffffffu, p, 16);
                p += __shfl_xor_sync(0xffffffffu, p, 8);
                p += __shfl_xor_sync(0xffffffffu, p, 4);
                p += __shfl_xor_sync(0xffffffffu, p, 2);
                p += __shfl_xor_sync(0xffffffffu, p, 1);
                f = g_fbase[(t - 1) * B_ + b] + p;
            }
            int tb = (t > 0) ? (t - 1) : 0;
            const float2* Bp   = (const float2*)(B_st + (size_t)tb * N_);
            const float2* crow = (const float2*)(g_c[rpar] + (size_t)b * N_);
            const float2* hrow = (const float2*)((t == 0)
                                   ? (h0 + (size_t)b * N_)
                                   : (out + ((size_t)b * T_ + (t - 1)) * N_));
#pragma unroll
            for (int k = 0; k < 8; ++k) {
                int j2 = k * 32 + lane;           // float2 index within row
                float2 c2 = __ldcg(&crow[j2]);
                float2 h2 = __ldcg(&hrow[j2]);
                float2 b2 = __ldg(&Bp[j2]);
                float2 cc;
                cc.x = c2.x + f * b2.x;
                cc.y = c2.y + f * b2.y;
                *(float2*)(sm + SM_CS + bL * 520 + j2 * 2) = cc;
                *(float2*)(sm + SM_HS + bL * 520 + j2 * 2) = h2;
            }
        }
        __syncthreads();

        // --- main dots: j-pair f32x2, 4i x 2b per thread, 16 j4 iters ---
        ull G[4][2], Aa[4][2];
#pragma unroll
        for (int r = 0; r < 4; ++r)
#pragma unroll
            for (int s = 0; s < 2; ++s) { G[r][s] = 0ull; Aa[r][s] = 0ull; }

#pragma unroll 2
        for (int q = 0; q < 16; ++q) {
            int cur = q & 1;
            if (q < 15) {
#pragma unroll
                for (int r = 0; r < 4; ++r)
                    av[cur ^ 1][r] = __ldg(pa + (size_t)(q + 1) * 512 + r * 8);
            }
            ulonglong2 cv[2], hv[2];
#pragma unroll
            for (int s = 0; s < 2; ++s) {
                cv[s] = csq0[q + s * 520];
                hv[s] = hsq0[q + s * 520];
            }
#pragma unroll
            for (int r = 0; r < 4; ++r) {
                ulonglong2 wi2 = wiq0[q * 32 + r * 8];
                ulonglong2 wh2 = whq0[q * 32 + r * 8];
                ulonglong2 a2  = av[cur][r];
#pragma unroll
                for (int s = 0; s < 2; ++s) {
                    G[r][s]  = fma2(wi2.x, cv[s].x, G[r][s]);
                    G[r][s]  = fma2(wi2.y, cv[s].y, G[r][s]);
                    G[r][s]  = fma2(wh2.x, hv[s].x, G[r][s]);
                    G[r][s]  = fma2(wh2.y, hv[s].y, G[r][s]);
                    Aa[r][s] = fma2(a2.x,  cv[s].x, Aa[r][s]);
                    Aa[r][s] = fma2(a2.y,  cv[s].y, Aa[r][s]);
                }
            }
        }

        // pack (gate, ahat) per output; m = r*2 + s
        ull pk[8];
#pragma unroll
        for (int r = 0; r < 4; ++r)
#pragma unroll
            for (int s = 0; s < 2; ++s) {
                float ga, gb, aa, ab;
                unpack2(G[r][s], ga, gb);
                unpack2(Aa[r][s], aa, ab);
                pk[r * 2 + s] = pack2(ga + gb, aa + ab);
            }

        // --- reduction round 1: kq 4..7 dump (groups 0..7) ---
        if (kq >= 4) {
            int g = bh * 4 + (kq - 4);
#pragma unroll
            for (int m = 0; m < 8; ++m) red[((g << 3) + m) * 32 + lane] = pk[m];
        }
        __syncthreads();
        // round 2: kq 0..3 add; kq 2..3 dump (groups 8..11)
        if (kq < 4) {
            int g = bh * 4 + kq;
#pragma unroll
            for (int m = 0; m < 8; ++m) pk[m] = add2(pk[m], red[((g << 3) + m) * 32 + lane]);
            if (kq >= 2) {
                int g2 = 8 + bh * 2 + (kq - 2);
#pragma unroll
                for (int m = 0; m < 8; ++m) red[((g2 << 3) + m) * 32 + lane] = pk[m];
            }
        }
        __syncthreads();
        // round 3: kq 0..1 add; swap-dump complement (groups 0..1)
        if (kq < 2) {
            int g2 = 8 + bh * 2 + kq;
#pragma unroll
            for (int m = 0; m < 8; ++m) pk[m] = add2(pk[m], red[((g2 << 3) + m) * 32 + lane]);
            int mlo = kq ? 0 : 4;   // dump the half the partner owns
#pragma unroll
            for (int mm = 0; mm < 4; ++mm) {
                int m = mlo + mm;
                red[((bh << 3) + m) * 32 + lane] = pk[m];
            }
        }
        __syncthreads();

        // --- epilogue on 4 warps: (kq<2, bh); kq0 owns r{0,1}, kq1 owns r{2,3} ---
        if (kq < 2) {
            int mown = kq ? 4 : 0;
#pragma unroll
            for (int mm = 0; mm < 4; ++mm) {
                int m = mown + mm;
                pk[m] = add2(pk[m], red[((bh << 3) + m) * 32 + lane]);
            }
#pragma unroll
            for (int s = 0; s < 2; ++s) {
                int bL = 8 * bh + bg + 4 * s, bG = bb0 + bL;
                float xv = __ldg(&x[(size_t)bG * T_ + t]);
                float fp = 0.0f;
#pragma unroll
                for (int rr = 0; rr < 2; ++rr) {
                    int r = (kq << 1) + rr;
                    int m = r * 2 + s;
                    int iL = ig + 8 * r, iG = i0 + iL;
                    float gsum, asum;
                    unpack2(pk[m], gsum, asum);
                    float gate = gsum + bias_s[iL] + w0_s[iL] * xv;
                    float o = 1.0f / (1.0f + __expf(-gate));
                    float ce = sm[SM_CS + bL * 520 + iG];
                    float h = o * tanhf(ce);
                    out[((size_t)bG * T_ + t) * N_ + iG] = h;
                    fp += wf_s[iL] * h;
                    __stcg(&g_c[wpar][(size_t)bG * N_ + iG], asum);
                }
                // reduce fp over the 8 ig lanes (bits 0..2 of lane)
                fp += __shfl_xor_sync(0xffffffffu, fp, 1);
                fp += __shfl_xor_sync(0xffffffffu, fp, 2);
                fp += __shfl_xor_sync(0xffffffffu, fp, 4);
                if (ig == 0) redf[bL * 2 + kq] = fp;
            }
        }
        __syncthreads();

        // --- per-block f partial (deterministic order) ---
        if (tid < 16)
            __stcg(&g_fp[t & 1][(bb0 + tid) * 16 + it], redf[tid * 2] + redf[tid * 2 + 1]);

        if (t != T_ - 1) grid_barrier();
    }
}

// ---------------------------------------------------------------------------
// Final: c_f = c-hat_{511} + f_{511} * B_{511}
// ---------------------------------------------------------------------------
__global__ void k_final(const float* __restrict__ B_st, float* __restrict__ outc) {
    int idx = blockIdx.x * blockDim.x + threadIdx.x;
    if (idx >= B_ * N_) return;
    int b = idx >> 9, i = idx & 511;
    float f = g_fbase[(T_ - 1) * B_ + b];
#pragma unroll
    for (int k = 0; k < 16; ++k) f += g_fp[1][b * 16 + k];
    outc[idx] = g_c[0][idx] + f * __ldg(&B_st[(size_t)(T_ - 1) * N_ + i]);
}

extern "C" void kernel_launch(void* const* d_in, const int* in_sizes, int n_in,
                              void* d_out, int out_size) {
    const float* x  = (const float*)d_in[0];
    const float* h0 = (const float*)d_in[1];
    const float* c0 = (const float*)d_in[2];
    const float* Wi = (const float*)d_in[3];
    const float* bi = (const float*)d_in[4];
    const float* Wh = (const float*)d_in[5];
    const float* bh = (const float*)d_in[6];
    const float* Wf = (const float*)d_in[7];
    const float* bf = (const float*)d_in[8];
    const float* A  = (const float*)d_in[9];
    const float* Bs = (const float*)d_in[10];
    float* out = (float*)d_out;

    cudaFuncSetAttribute(hippo_main, cudaFuncAttributeMaxDynamicSharedMemorySize, SMEM_BYTES);

    k_apack<<<dim3(16, 16, 512), dim3(32, 8)>>>(A);
    k_wpack<<<2048, 256>>>(Wi, Wh);
    k_init<<<256, 256>>>(x, c0, Wf, bf);
    hippo_main<<<NBLK, NTHR, SMEM_BYTES>>>(x, h0, Wi, bi, Wh, bh, Wf, Bs, out);
    k_final<<<256, 256>>>(Bs, out + (size_t)B_ * T_ * N_);
}